// round 3
// baseline (speedup 1.0000x reference)
#include <cuda_runtime.h>
#include <cstdint>

#define T_STEPS 512
#define BATCH   64
#define INDIM   1024
#define HID     1024
#define G4      4096

// scan config
#define NBLK     128
#define SCAN_THR 256
#define KC       32          // k-chunk per staging buffer
// xg config
#define XG_BM  64
#define XG_BN  64
#define XG_KC  32
#define XG_THR 256

// ---------------------------------------------------------------------------
__device__ float g_xg[(size_t)T_STEPS * BATCH * G4];   // [t][b][j'] permuted cols
__device__ float g_h2[2][HID * 2 * BATCH];             // DUPLICATED h: [k][2b], double buffered
__device__ unsigned int g_count;
__device__ unsigned int g_sense;

// packed f32x2 helpers
__device__ __forceinline__ void fma2(unsigned long long& d,
                                     unsigned long long a,
                                     unsigned long long b) {
    asm("fma.rn.f32x2 %0, %1, %2, %0;" : "+l"(d) : "l"(a), "l"(b));
}
__device__ __forceinline__ void add2(unsigned long long& d, unsigned long long a) {
    asm("add.rn.f32x2 %0, %0, %1;" : "+l"(d) : "l"(a));
}
__device__ __forceinline__ float2 unpack2(unsigned long long v) {
    float2 r;
    asm("mov.b64 {%0, %1}, %2;" : "=f"(r.x), "=f"(r.y) : "l"(v));
    return r;
}
__device__ __forceinline__ float sigf(float x) {
    return __fdividef(1.0f, 1.0f + __expf(-x));
}
__device__ __forceinline__ float tanh_fast(float x) {
    return __fdividef(2.0f, 1.0f + __expf(-2.0f * x)) - 1.0f;
}

// ---------------------------------------------------------------------------
// xg GEMM (+ fused reset). MOV-free inner loop:
//   acc2[r][cp] += (a_r, a_r) * (w_c, w_c+1)
//   A staged DUPLICATED in smem [kk][2*row]; W staged [kk][col] (natural pairs).
// ---------------------------------------------------------------------------
__global__ __launch_bounds__(XG_THR, 3) void xg_gemm(
    const float* __restrict__ x,
    const float* __restrict__ Wih,
    const float* __restrict__ bih,
    const float* __restrict__ bhh)
{
    __shared__ float As[2][XG_KC * 128];  // dup rows: [kk][2*row], 16 KB each
    __shared__ float Ws[2][XG_KC * 64];   // [kk][col], 8 KB each

    const int tid = threadIdx.x;
    const int tx  = tid & 15;    // cols c0 = 4*tx
    const int ty  = tid >> 4;    // rows r0 = 4*ty
    const int n0  = blockIdx.x * XG_BN;
    const int m0  = blockIdx.y * XG_BM;

    // fused reset (one block; scan runs in a later launch)
    if (blockIdx.x == 0 && blockIdx.y == 0) {
        float4* hz = reinterpret_cast<float4*>(&g_h2[0][0]);
#pragma unroll
        for (int u = 0; u < 128; u++) hz[tid + XG_THR * u] = make_float4(0.f, 0.f, 0.f, 0.f);
        if (tid == 0) { g_count = 0u; g_sense = 0u; }
    }

    // staging mappings
    const int a_row = tid & 63;
    const int a_k8  = (tid >> 6) * 8;    // 0,8,16,24
    const int w_col = tid & 63;
    const int w_k8  = (tid >> 6) * 8;

    const int np   = n0 + w_col;
    const int jo_w = (np & 3) * HID + (np >> 2);   // permuted col -> original W row
    const float* wrow = Wih + (size_t)jo_w * INDIM;
    const float* arow = x   + (size_t)(m0 + a_row) * INDIM;

    unsigned long long acc[4][2];
#pragma unroll
    for (int r = 0; r < 4; r++) { acc[r][0] = 0ull; acc[r][1] = 0ull; }

    float4 pa0 = *reinterpret_cast<const float4*>(arow + a_k8);
    float4 pa1 = *reinterpret_cast<const float4*>(arow + a_k8 + 4);
    float4 pw0 = *reinterpret_cast<const float4*>(wrow + w_k8);
    float4 pw1 = *reinterpret_cast<const float4*>(wrow + w_k8 + 4);

    int buf = 0;
#pragma unroll 1
    for (int kb = 0; kb < INDIM; kb += XG_KC) {
        // stage A duplicated: As[kk][2*row] = As[kk][2*row+1] = x[row][kk]
        {
            float2* ad = reinterpret_cast<float2*>(As[buf]);
            const float av[8] = {pa0.x, pa0.y, pa0.z, pa0.w, pa1.x, pa1.y, pa1.z, pa1.w};
#pragma unroll
            for (int i = 0; i < 8; i++)
                ad[(a_k8 + i) * 64 + a_row] = make_float2(av[i], av[i]);
        }
        {   // stage W transposed: Ws[kk][col]
            const float wv[8] = {pw0.x, pw0.y, pw0.z, pw0.w, pw1.x, pw1.y, pw1.z, pw1.w};
#pragma unroll
            for (int i = 0; i < 8; i++)
                Ws[buf][(w_k8 + i) * 64 + w_col] = wv[i];
        }
        __syncthreads();

        if (kb + XG_KC < INDIM) {
            pa0 = *reinterpret_cast<const float4*>(arow + kb + XG_KC + a_k8);
            pa1 = *reinterpret_cast<const float4*>(arow + kb + XG_KC + a_k8 + 4);
            pw0 = *reinterpret_cast<const float4*>(wrow + kb + XG_KC + w_k8);
            pw1 = *reinterpret_cast<const float4*>(wrow + kb + XG_KC + w_k8 + 4);
        }

        const float* ab = As[buf];
        const float* wb = Ws[buf];
#pragma unroll 16
        for (int kk = 0; kk < XG_KC; kk++) {
            ulonglong2 wp  = *reinterpret_cast<const ulonglong2*>(wb + kk * 64 + tx * 4);
            ulonglong2 a01 = *reinterpret_cast<const ulonglong2*>(ab + kk * 128 + ty * 8);
            ulonglong2 a23 = *reinterpret_cast<const ulonglong2*>(ab + kk * 128 + ty * 8 + 4);
            fma2(acc[0][0], a01.x, wp.x);  fma2(acc[0][1], a01.x, wp.y);
            fma2(acc[1][0], a01.y, wp.x);  fma2(acc[1][1], a01.y, wp.y);
            fma2(acc[2][0], a23.x, wp.x);  fma2(acc[2][1], a23.x, wp.y);
            fma2(acc[3][0], a23.y, wp.x);  fma2(acc[3][1], a23.y, wp.y);
        }
        buf ^= 1;
    }

    float bias[4];
#pragma unroll
    for (int cc = 0; cc < 4; cc++) {
        int np2 = n0 + tx * 4 + cc;
        int jo  = (np2 & 3) * HID + (np2 >> 2);
        bias[cc] = bih[jo] + bhh[jo];
    }
#pragma unroll
    for (int r = 0; r < 4; r++) {
        float2 u0 = unpack2(acc[r][0]);
        float2 u1 = unpack2(acc[r][1]);
        int m = m0 + ty * 4 + r;
        *reinterpret_cast<float4*>(&g_xg[(size_t)m * G4 + n0 + tx * 4]) =
            make_float4(u0.x + bias[0], u0.y + bias[1], u1.x + bias[2], u1.y + bias[3]);
    }
}

// ---------------------------------------------------------------------------
// grid barrier
// ---------------------------------------------------------------------------
__device__ __forceinline__ void grid_bar(unsigned int target) {
    __threadfence();
    __syncthreads();
    if (threadIdx.x == 0) {
        unsigned int a = atomicAdd(&g_count, 1u);
        if (a == NBLK - 1) {
            atomicExch(&g_count, 0u);
            __threadfence();
            atomicExch(&g_sense, target);
        } else {
            volatile unsigned int* s = &g_sense;
            while (*s < target) { __nanosleep(16); }
            __threadfence();
        }
    }
    __syncthreads();
}

// ---------------------------------------------------------------------------
// Persistent LSTM scan, MOV-free inner loop (11 instr / 16 MAC per thread-kk).
//   Block jt: 32 permuted cols = 8 hj. W_hh [k][32] persistent in smem (128 KB).
//   h kept DUPLICATED in global [k][2b]; staged chunks are straight copies.
//   Split-K(2): threads 0-127 k=[0,512), threads 128-255 k=[512,1024).
// ---------------------------------------------------------------------------
#define SCAN_SMEM_FLOATS (32768 + 16384 + 2048)   // ws + hs[2][2] + red = 200 KB

__global__ __launch_bounds__(SCAN_THR, 1) void lstm_scan(
    const float* __restrict__ Whh,
    float* __restrict__ out)
{
    extern __shared__ float sm[];
    float* ws = sm;                        // [1024][32]
    float* hs = sm + 32768;                // 4 bufs x (KC*128) floats
    unsigned long long* red =
        reinterpret_cast<unsigned long long*>(sm + 32768 + 16384);  // 1024 ull

    const int tid = threadIdx.x;
    const int ks  = tid >> 7;              // K-half
    const int txy = tid & 127;
    const int tx  = txy & 7;               // hj-local; cols c0..c0+3 (i,f,g,o)
    const int ty  = txy >> 3;              // rows b0..b0+3
    const int b0  = ty * 4;
    const int c0  = tx * 4;
    const int jt  = blockIdx.x;
    const int j0  = jt * 32;
    const int hj  = jt * 8 + tx;

    // persistent W_hh preload: ws[k][col]
    {
        const int wcol  = tid & 31;
        const int kpart = tid >> 5;        // 8 parts x 128 k
        const int jp = j0 + wcol;
        const int jo = (jp & 3) * HID + (jp >> 2);
        const float* wr = Whh + (size_t)jo * HID + kpart * 128;
#pragma unroll 8
        for (int i = 0; i < 128; i += 4) {
            float4 v = *reinterpret_cast<const float4*>(wr + i);
            int k = kpart * 128 + i;
            ws[(k + 0) * 32 + wcol] = v.x;
            ws[(k + 1) * 32 + wcol] = v.y;
            ws[(k + 2) * 32 + wcol] = v.z;
            ws[(k + 3) * 32 + wcol] = v.w;
        }
    }
    __syncthreads();

    float* hbase = hs + ks * 2 * (KC * 128);
    const int ksk = ks * 512;              // this half's k offset

    float c_[4] = {0.f, 0.f, 0.f, 0.f};
    int buf = 0;

#pragma unroll 1
    for (int t = 0; t < T_STEPS; t++) {
        const int cur = t & 1, nxt = cur ^ 1;
        const float* hsrc = g_h2[cur];

        // xg epilogue prefetch (independent, hidden by k-loop)
        float4 xr[4];
        if (ks == 0) {
            const float* xgp = g_xg + (size_t)t * (BATCH * G4) + j0 + c0;
#pragma unroll
            for (int r = 0; r < 4; r++)
                xr[r] = *reinterpret_cast<const float4*>(xgp + (size_t)(b0 + r) * G4);
        }

        unsigned long long acc[4][2];
#pragma unroll
        for (int r = 0; r < 4; r++) { acc[r][0] = 0ull; acc[r][1] = 0ull; }

        // prefetch chunk 0 (dup layout -> straight copy)
        float4 hr[8];
        {
            const float4* hg = reinterpret_cast<const float4*>(hsrc + ksk * 128);
#pragma unroll
            for (int u = 0; u < 8; u++) hr[u] = __ldcg(hg + txy + 128 * u);
        }

#pragma unroll 1
        for (int cidx = 0; cidx < 16; cidx++) {
            float* hb = hbase + buf * (KC * 128);
            {
                float4* hd = reinterpret_cast<float4*>(hb);
#pragma unroll
                for (int u = 0; u < 8; u++) hd[txy + 128 * u] = hr[u];
            }
            __syncthreads();

            if (cidx < 15) {
                const float4* hg = reinterpret_cast<const float4*>(
                    hsrc + (ksk + (cidx + 1) * KC) * 128);
#pragma unroll
                for (int u = 0; u < 8; u++) hr[u] = __ldcg(hg + txy + 128 * u);
            }

            const float* wsc = ws + (ksk + cidx * KC) * 32;
#pragma unroll 16
            for (int kk = 0; kk < KC; kk++) {
                ulonglong2 wp  = *reinterpret_cast<const ulonglong2*>(wsc + kk * 32 + c0);
                ulonglong2 h01 = *reinterpret_cast<const ulonglong2*>(hb + kk * 128 + b0 * 2);
                ulonglong2 h23 = *reinterpret_cast<const ulonglong2*>(hb + kk * 128 + b0 * 2 + 4);
                fma2(acc[0][0], h01.x, wp.x);  fma2(acc[0][1], h01.x, wp.y);
                fma2(acc[1][0], h01.y, wp.x);  fma2(acc[1][1], h01.y, wp.y);
                fma2(acc[2][0], h23.x, wp.x);  fma2(acc[2][1], h23.x, wp.y);
                fma2(acc[3][0], h23.y, wp.x);  fma2(acc[3][1], h23.y, wp.y);
            }
            buf ^= 1;
        }

        // split-K reduction
        if (ks == 1) {
            ulonglong2* rp = reinterpret_cast<ulonglong2*>(red + txy * 8);
            rp[0] = make_ulonglong2(acc[0][0], acc[0][1]);
            rp[1] = make_ulonglong2(acc[1][0], acc[1][1]);
            rp[2] = make_ulonglong2(acc[2][0], acc[2][1]);
            rp[3] = make_ulonglong2(acc[3][0], acc[3][1]);
        }
        __syncthreads();

        if (ks == 0) {
            const ulonglong2* rp = reinterpret_cast<const ulonglong2*>(red + txy * 8);
#pragma unroll
            for (int r = 0; r < 4; r++) {
                ulonglong2 rv = rp[r];
                add2(acc[r][0], rv.x);
                add2(acc[r][1], rv.y);
            }

            float hn[4];
#pragma unroll
            for (int r = 0; r < 4; r++) {
                float2 u0 = unpack2(acc[r][0]);   // cols (i, f)
                float2 u1 = unpack2(acc[r][1]);   // cols (g, o)
                float gi = sigf(u0.x + xr[r].x);
                float gf = sigf(u0.y + xr[r].y);
                float gg = tanh_fast(u1.x + xr[r].z);
                float go = sigf(u1.y + xr[r].w);
                c_[r]  = gf * c_[r] + gi * gg;
                hn[r]  = go * tanh_fast(c_[r]);
            }
            // duplicated h store: [hj][2b]
            float* hdst = g_h2[nxt] + hj * 128 + b0 * 2;
            *reinterpret_cast<float4*>(hdst)     = make_float4(hn[0], hn[0], hn[1], hn[1]);
            *reinterpret_cast<float4*>(hdst + 4) = make_float4(hn[2], hn[2], hn[3], hn[3]);
            if (t == T_STEPS - 1) {
#pragma unroll
                for (int r = 0; r < 4; r++)
                    out[(b0 + r) * HID + hj] = hn[r];
            }
        }

        if (t != T_STEPS - 1) grid_bar((unsigned int)(t + 1));
    }
}

// ---------------------------------------------------------------------------
extern "C" void kernel_launch(void* const* d_in, const int* in_sizes, int n_in,
                              void* d_out, int out_size) {
    const float* x   = (const float*)d_in[0];
    const float* Wih = (const float*)d_in[1];
    const float* Whh = (const float*)d_in[2];
    const float* bih = (const float*)d_in[3];
    const float* bhh = (const float*)d_in[4];
    float* out = (float*)d_out;

    cudaFuncSetAttribute(lstm_scan, cudaFuncAttributeMaxDynamicSharedMemorySize,
                         SCAN_SMEM_FLOATS * 4);

    xg_gemm<<<dim3(G4 / XG_BN, (T_STEPS * BATCH) / XG_BM), XG_THR>>>(x, Wih, bih, bhh);
    lstm_scan<<<NBLK, SCAN_THR, SCAN_SMEM_FLOATS * 4>>>(Whh, out);
}

// round 5
// speedup vs baseline: 2.0057x; 2.0057x over previous
#include <cuda_runtime.h>
#include <cuda_bf16.h>
#include <cstdint>

#define T_STEPS 512
#define BATCH   64
#define INDIM   1024
#define HID     1024
#define G4      4096

// scan config (R2, proven)
#define NBLK     128
#define SCAN_THR 256
#define KC       64
#define SCAN_SMEM_FLOATS (32768 + 16384 + 2048)   // 200 KB

// xg mma config
#define MM_BM   128
#define MM_BN   128
#define MM_KC   64          // bf16 per chunk = one 128-B SW128 row
#define MM_THR  256

// ---------------------------------------------------------------------------
// Global scratch
// ---------------------------------------------------------------------------
__device__ float g_xg[(size_t)T_STEPS * BATCH * G4];   // [m][j'] permuted, bias included
__device__ float g_h[2][HID * BATCH];                  // [hj][b] double buffered
__device__ __nv_bfloat16 g_xh[(size_t)T_STEPS * BATCH * INDIM];
__device__ __nv_bfloat16 g_xl[(size_t)T_STEPS * BATCH * INDIM];
__device__ __nv_bfloat16 g_wh[(size_t)G4 * INDIM];     // permuted rows
__device__ __nv_bfloat16 g_wl[(size_t)G4 * INDIM];
__device__ float g_bias[G4];
__device__ unsigned int g_count;
__device__ unsigned int g_sense;

// ---------------------------------------------------------------------------
// Ampere-ISA helpers (supported on plain compute_103)
// ---------------------------------------------------------------------------
__device__ __forceinline__ uint32_t smem_to_u32(const void* p) {
    uint32_t a;
    asm("{ .reg .u64 t; cvta.to.shared.u64 t, %1; cvt.u32.u64 %0, t; }" : "=r"(a) : "l"(p));
    return a;
}
__device__ __forceinline__ void ldmx4(uint32_t& r0, uint32_t& r1, uint32_t& r2,
                                      uint32_t& r3, uint32_t a) {
    asm volatile("ldmatrix.sync.aligned.m8n8.x4.shared.b16 {%0,%1,%2,%3}, [%4];"
                 : "=r"(r0), "=r"(r1), "=r"(r2), "=r"(r3) : "r"(a));
}
__device__ __forceinline__ void mma16816(float* d, const uint32_t* a, const uint32_t* b) {
    asm volatile(
        "mma.sync.aligned.m16n8k16.row.col.f32.bf16.bf16.f32 "
        "{%0,%1,%2,%3},{%4,%5,%6,%7},{%8,%9},{%0,%1,%2,%3};"
        : "+f"(d[0]), "+f"(d[1]), "+f"(d[2]), "+f"(d[3])
        : "r"(a[0]), "r"(a[1]), "r"(a[2]), "r"(a[3]), "r"(b[0]), "r"(b[1]));
}
#define CP_ASYNC16(s, g) \
    asm volatile("cp.async.cg.shared.global [%0], [%1], 16;" :: "r"(s), "l"(g) : "memory")
#define CP_COMMIT()  asm volatile("cp.async.commit_group;" ::: "memory")
#define CP_WAIT0()   asm volatile("cp.async.wait_group 0;" ::: "memory")

// ---------------------------------------------------------------------------
// FFMA2 / math helpers (scan)
// ---------------------------------------------------------------------------
__device__ __forceinline__ unsigned long long pack2(float lo, float hi) {
    unsigned long long r;
    asm("mov.b64 %0, {%1, %2};" : "=l"(r) : "f"(lo), "f"(hi));
    return r;
}
__device__ __forceinline__ void fma2(unsigned long long& d, unsigned long long a,
                                     unsigned long long b) {
    asm("fma.rn.f32x2 %0, %1, %2, %0;" : "+l"(d) : "l"(a), "l"(b));
}
__device__ __forceinline__ void add2(unsigned long long& d, unsigned long long a) {
    asm("add.rn.f32x2 %0, %0, %1;" : "+l"(d) : "l"(a));
}
__device__ __forceinline__ float2 unpack2(unsigned long long v) {
    float2 r;
    asm("mov.b64 {%0, %1}, %2;" : "=f"(r.x), "=f"(r.y) : "l"(v));
    return r;
}
__device__ __forceinline__ float sigf(float x) {
    return __fdividef(1.0f, 1.0f + __expf(-x));
}
__device__ __forceinline__ float tanh_fast(float x) {
    return __fdividef(2.0f, 1.0f + __expf(-2.0f * x)) - 1.0f;
}

// ---------------------------------------------------------------------------
// Conversion: bf16 hi/lo splits of x and permuted W_ih, bias, resets
// ---------------------------------------------------------------------------
#define CV_XU 8388608u
#define CV_WU 1048576u
#define CV_BU 1024u
#define CV_HU 32768u
#define CV_GRID 36996u

__global__ void convert_inputs(const float* __restrict__ x,
                               const float* __restrict__ Wih,
                               const float* __restrict__ bih,
                               const float* __restrict__ bhh) {
    unsigned u = blockIdx.x * 256u + threadIdx.x;
    if (u < CV_XU) {
        float4 v = __ldg((const float4*)x + u);
        __nv_bfloat162 h01 = __floats2bfloat162_rn(v.x, v.y);
        __nv_bfloat162 h23 = __floats2bfloat162_rn(v.z, v.w);
        __nv_bfloat162 l01 = __floats2bfloat162_rn(v.x - __bfloat162float(h01.x),
                                                   v.y - __bfloat162float(h01.y));
        __nv_bfloat162 l23 = __floats2bfloat162_rn(v.z - __bfloat162float(h23.x),
                                                   v.w - __bfloat162float(h23.y));
        *(__nv_bfloat162*)(g_xh + (size_t)u * 4)     = h01;
        *(__nv_bfloat162*)(g_xh + (size_t)u * 4 + 2) = h23;
        *(__nv_bfloat162*)(g_xl + (size_t)u * 4)     = l01;
        *(__nv_bfloat162*)(g_xl + (size_t)u * 4 + 2) = l23;
    } else if (u < CV_XU + CV_WU) {
        unsigned uw = u - CV_XU;
        int np = uw >> 8;
        int kq = uw & 255;
        int jo = (np & 3) * HID + (np >> 2);
        float4 v = __ldg((const float4*)(Wih + (size_t)jo * INDIM) + kq);
        __nv_bfloat162 h01 = __floats2bfloat162_rn(v.x, v.y);
        __nv_bfloat162 h23 = __floats2bfloat162_rn(v.z, v.w);
        __nv_bfloat162 l01 = __floats2bfloat162_rn(v.x - __bfloat162float(h01.x),
                                                   v.y - __bfloat162float(h01.y));
        __nv_bfloat162 l23 = __floats2bfloat162_rn(v.z - __bfloat162float(h23.x),
                                                   v.w - __bfloat162float(h23.y));
        size_t base = (size_t)np * INDIM + kq * 4;
        *(__nv_bfloat162*)(g_wh + base)     = h01;
        *(__nv_bfloat162*)(g_wh + base + 2) = h23;
        *(__nv_bfloat162*)(g_wl + base)     = l01;
        *(__nv_bfloat162*)(g_wl + base + 2) = l23;
    } else if (u < CV_XU + CV_WU + CV_BU) {
        unsigned ub = u - CV_XU - CV_WU;
        if (ub == 0) { g_count = 0u; g_sense = 0u; }
#pragma unroll
        for (int c = 0; c < 4; c++) {
            int np = ub * 4 + c;
            int jo = (np & 3) * HID + (np >> 2);
            g_bias[np] = bih[jo] + bhh[jo];
        }
    } else if (u < CV_XU + CV_WU + CV_BU + CV_HU) {
        unsigned uh = u - CV_XU - CV_WU - CV_BU;
        reinterpret_cast<float4*>(&g_h[0][0])[uh] = make_float4(0.f, 0.f, 0.f, 0.f);
    }
}

// ---------------------------------------------------------------------------
// xg via mma.sync bf16 (3-term split), cp.async double-buffered.
//   SMEM per buffer: AH|AL|BH|BL, each 128 rows x 128 B (SW128 swizzle).
// ---------------------------------------------------------------------------
#define XR_AH 0
#define XR_AL 16384
#define XR_BH 32768
#define XR_BL 49152
#define XR_BUF 65536
#define XS_TOTAL (2 * XR_BUF)

__global__ __launch_bounds__(MM_THR, 1) void xg_mma() {
    extern __shared__ char smem[];
    const uint32_t sb = smem_to_u32(smem);
    const int tid = threadIdx.x;
    const int lid = tid & 31;
    const int wid = tid >> 5;
    const int wm  = wid & 3;         // warp m: 4 x 32 rows
    const int wn  = wid >> 2;        // warp n: 2 x 64 cols
    const int n0  = blockIdx.x * MM_BN;
    const int m0  = blockIdx.y * MM_BM;

    // staging lane mapping (16B units)
    const int s_row = tid >> 3;         // 0..31, +32 per pass
    const int s_c16 = tid & 7;

    // ldmatrix lane mappings
    const int a_ml = lid & 15;          // m within 16
    const int a_kh = (lid >> 4) & 1;    // k half
    const int b_nl = (lid & 7) + ((lid & 16) ? 8 : 0);
    const int b_kh = (lid >> 3) & 1;

    float acc[2][8][4];
#pragma unroll
    for (int i = 0; i < 2; i++)
#pragma unroll
        for (int j = 0; j < 8; j++)
#pragma unroll
            for (int q = 0; q < 4; q++) acc[i][j][q] = 0.f;

    // stage chunk helper (lambda via macro-ish inline)
    auto stage = [&](int c, int buf) {
        const int kb = c * MM_KC;
        const uint32_t base = sb + buf * XR_BUF;
#pragma unroll
        for (int p = 0; p < 4; p++) {
            int row = s_row + p * 32;
            uint32_t so = (uint32_t)(row * 128 + ((s_c16 ^ (row & 7)) * 16));
            const __nv_bfloat16* ah = g_xh + (size_t)(m0 + row) * INDIM + kb + s_c16 * 8;
            const __nv_bfloat16* al = g_xl + (size_t)(m0 + row) * INDIM + kb + s_c16 * 8;
            const __nv_bfloat16* bh = g_wh + (size_t)(n0 + row) * INDIM + kb + s_c16 * 8;
            const __nv_bfloat16* bl = g_wl + (size_t)(n0 + row) * INDIM + kb + s_c16 * 8;
            CP_ASYNC16(base + XR_AH + so, ah);
            CP_ASYNC16(base + XR_AL + so, al);
            CP_ASYNC16(base + XR_BH + so, bh);
            CP_ASYNC16(base + XR_BL + so, bl);
        }
        CP_COMMIT();
    };

    stage(0, 0);

#pragma unroll 1
    for (int c = 0; c < 16; c++) {
        CP_WAIT0();
        __syncthreads();
        if (c < 15) stage(c + 1, (c + 1) & 1);

        const uint32_t base = sb + (c & 1) * XR_BUF;
#pragma unroll
        for (int kk = 0; kk < 4; kk++) {
            // A fragments (hi & lo), 2 m16 frags each
            uint32_t ahf[2][4], alf[2][4];
#pragma unroll
            for (int mf = 0; mf < 2; mf++) {
                int r = wm * 32 + mf * 16 + a_ml;
                uint32_t co = (uint32_t)((((kk * 2 + a_kh) ^ (r & 7)) * 16) + r * 128);
                ldmx4(ahf[mf][0], ahf[mf][1], ahf[mf][2], ahf[mf][3], base + XR_AH + co);
                ldmx4(alf[mf][0], alf[mf][1], alf[mf][2], alf[mf][3], base + XR_AL + co);
            }
            // B in pairs of n8 frags
#pragma unroll
            for (int np = 0; np < 4; np++) {
                int r = wn * 64 + np * 16 + b_nl;
                uint32_t co = (uint32_t)((((kk * 2 + b_kh) ^ (r & 7)) * 16) + r * 128);
                uint32_t bh[4], bl[4];
                ldmx4(bh[0], bh[1], bh[2], bh[3], base + XR_BH + co);
                ldmx4(bl[0], bl[1], bl[2], bl[3], base + XR_BL + co);
#pragma unroll
                for (int mf = 0; mf < 2; mf++) {
                    mma16816(acc[mf][np * 2 + 0], ahf[mf], &bh[0]);
                    mma16816(acc[mf][np * 2 + 1], ahf[mf], &bh[2]);
                    mma16816(acc[mf][np * 2 + 0], ahf[mf], &bl[0]);
                    mma16816(acc[mf][np * 2 + 1], ahf[mf], &bl[2]);
                    mma16816(acc[mf][np * 2 + 0], alf[mf], &bh[0]);
                    mma16816(acc[mf][np * 2 + 1], alf[mf], &bh[2]);
                }
            }
        }
        __syncthreads();
    }

    // epilogue: + bias -> g_xg
    const int lr = lid >> 2;
    const int lc = (lid & 3) * 2;
#pragma unroll
    for (int mf = 0; mf < 2; mf++) {
#pragma unroll
        for (int nf = 0; nf < 8; nf++) {
            int m = m0 + wm * 32 + mf * 16 + lr;
            int n = n0 + wn * 64 + nf * 8 + lc;
            float2 bv = __ldg((const float2*)(g_bias + n));
            float2 o0 = make_float2(acc[mf][nf][0] + bv.x, acc[mf][nf][1] + bv.y);
            float2 o1 = make_float2(acc[mf][nf][2] + bv.x, acc[mf][nf][3] + bv.y);
            *reinterpret_cast<float2*>(g_xg + (size_t)m * G4 + n)       = o0;
            *reinterpret_cast<float2*>(g_xg + (size_t)(m + 8) * G4 + n) = o1;
        }
    }
}

// ---------------------------------------------------------------------------
// grid barrier (R2)
// ---------------------------------------------------------------------------
__device__ __forceinline__ void grid_bar(unsigned int target) {
    __syncthreads();
    if (threadIdx.x == 0) {
        __threadfence();
        unsigned int a = atomicAdd(&g_count, 1u);
        if (a == NBLK - 1) {
            atomicExch(&g_count, 0u);
            __threadfence();
            atomicExch(&g_sense, target);
        } else {
            volatile unsigned int* s = &g_sense;
            while (*s < target) { __nanosleep(16); }
            __threadfence();
        }
    }
    __syncthreads();
}

// ---------------------------------------------------------------------------
// Persistent LSTM scan — R2 version (proven)
// ---------------------------------------------------------------------------
__global__ __launch_bounds__(SCAN_THR) void lstm_scan(
    const float* __restrict__ Whh,
    float* __restrict__ out)
{
    extern __shared__ float sm[];
    float* ws  = sm;                    // [1024][32]
    float* hsA = sm + 32768;            // [half][buf][64*64]
    float* red = sm + 32768 + 16384;    // [128][16]

    const int tid = threadIdx.x;
    const int ks  = tid >> 7;
    const int txy = tid & 127;
    const int tx  = txy & 7;
    const int ty  = txy >> 3;
    const int b0  = ty * 4;
    const int c0  = tx * 4;
    const int jt  = blockIdx.x;
    const int j0  = jt * 32;
    const int hj  = jt * 8 + tx;

    {   // persistent W_hh preload: ws[k][col]
        const int wcol  = tid & 31;
        const int kpart = tid >> 5;
        const int jp = j0 + wcol;
        const int jo = (jp & 3) * HID + (jp >> 2);
        const float* wr = Whh + (size_t)jo * HID + kpart * 128;
#pragma unroll 8
        for (int i = 0; i < 128; i += 4) {
            float4 v = *reinterpret_cast<const float4*>(wr + i);
            int k = kpart * 128 + i;
            ws[(k + 0) * 32 + wcol] = v.x;
            ws[(k + 1) * 32 + wcol] = v.y;
            ws[(k + 2) * 32 + wcol] = v.z;
            ws[(k + 3) * 32 + wcol] = v.w;
        }
    }
    __syncthreads();

    const float* wsme = ws + (ks * 512) * 32;

    float c_[4] = {0.f, 0.f, 0.f, 0.f};
    int buf = 0;

#pragma unroll 1
    for (int t = 0; t < T_STEPS; t++) {
        const int cur = t & 1, nxt = cur ^ 1;
        const float* hsrc = g_h[cur];

        float4 xr[4];
        if (ks == 0) {
            const float* xgp = g_xg + (size_t)t * (BATCH * G4) + j0 + c0;
#pragma unroll
            for (int r = 0; r < 4; r++)
                xr[r] = *reinterpret_cast<const float4*>(xgp + (size_t)(b0 + r) * G4);
        }

        unsigned long long acc[2][4];
#pragma unroll
        for (int p = 0; p < 2; p++)
#pragma unroll
            for (int cc = 0; cc < 4; cc++) acc[p][cc] = 0ull;

        float4 hr[8];
        {
            const float4* hg = reinterpret_cast<const float4*>(hsrc + (ks * 512) * BATCH);
#pragma unroll
            for (int u = 0; u < 8; u++) hr[u] = __ldcg(hg + txy + 128 * u);
        }

#pragma unroll 1
        for (int cidx = 0; cidx < 8; cidx++) {
            float* hb = hsA + (ks * 2 + buf) * 4096;
            {
                float4* hd = reinterpret_cast<float4*>(hb);
#pragma unroll
                for (int u = 0; u < 8; u++) hd[txy + 128 * u] = hr[u];
            }
            __syncthreads();

            if (cidx < 7) {
                const float4* hg = reinterpret_cast<const float4*>(
                    hsrc + (ks * 512 + (cidx + 1) * KC) * BATCH);
#pragma unroll
                for (int u = 0; u < 8; u++) hr[u] = __ldcg(hg + txy + 128 * u);
            }

            const float* wsc = wsme + (cidx * KC) * 32;
#pragma unroll 16
            for (int kk = 0; kk < KC; kk++) {
                ulonglong2 hp = *reinterpret_cast<const ulonglong2*>(hb + kk * BATCH + b0);
                float4 wv = *reinterpret_cast<const float4*>(wsc + kk * 32 + c0);
                unsigned long long w0 = pack2(wv.x, wv.x);
                unsigned long long w1 = pack2(wv.y, wv.y);
                unsigned long long w2 = pack2(wv.z, wv.z);
                unsigned long long w3 = pack2(wv.w, wv.w);
                fma2(acc[0][0], hp.x, w0);  fma2(acc[1][0], hp.y, w0);
                fma2(acc[0][1], hp.x, w1);  fma2(acc[1][1], hp.y, w1);
                fma2(acc[0][2], hp.x, w2);  fma2(acc[1][2], hp.y, w2);
                fma2(acc[0][3], hp.x, w3);  fma2(acc[1][3], hp.y, w3);
            }
            buf ^= 1;
        }

        if (ks == 1) {
            ulonglong2* rp = reinterpret_cast<ulonglong2*>(red + txy * 16);
            rp[0] = make_ulonglong2(acc[0][0], acc[0][1]);
            rp[1] = make_ulonglong2(acc[0][2], acc[0][3]);
            rp[2] = make_ulonglong2(acc[1][0], acc[1][1]);
            rp[3] = make_ulonglong2(acc[1][2], acc[1][3]);
        }
        __syncthreads();

        if (ks == 0) {
            const ulonglong2* rp = reinterpret_cast<const ulonglong2*>(red + txy * 16);
            ulonglong2 r0 = rp[0], r1 = rp[1], r2 = rp[2], r3 = rp[3];
            add2(acc[0][0], r0.x);  add2(acc[0][1], r0.y);
            add2(acc[0][2], r1.x);  add2(acc[0][3], r1.y);
            add2(acc[1][0], r2.x);  add2(acc[1][1], r2.y);
            add2(acc[1][2], r3.x);  add2(acc[1][3], r3.y);

            float gt[4][4];
#pragma unroll
            for (int cc = 0; cc < 4; cc++) {
                float2 lo = unpack2(acc[0][cc]);
                float2 hi = unpack2(acc[1][cc]);
                gt[0][cc] = lo.x;  gt[1][cc] = lo.y;
                gt[2][cc] = hi.x;  gt[3][cc] = hi.y;
            }
            float hn[4];
#pragma unroll
            for (int r = 0; r < 4; r++) {
                float gi = sigf(gt[r][0] + xr[r].x);
                float gf = sigf(gt[r][1] + xr[r].y);
                float gg = tanh_fast(gt[r][2] + xr[r].z);
                float go = sigf(gt[r][3] + xr[r].w);
                c_[r]  = gf * c_[r] + gi * gg;
                hn[r]  = go * tanh_fast(c_[r]);
            }
            *reinterpret_cast<float4*>(&g_h[nxt][hj * BATCH + b0]) =
                make_float4(hn[0], hn[1], hn[2], hn[3]);
            if (t == T_STEPS - 1) {
#pragma unroll
                for (int r = 0; r < 4; r++)
                    out[(b0 + r) * HID + hj] = hn[r];
            }
        }

        if (t != T_STEPS - 1) grid_bar((unsigned int)(t + 1));
    }
}

// ---------------------------------------------------------------------------
extern "C" void kernel_launch(void* const* d_in, const int* in_sizes, int n_in,
                              void* d_out, int out_size) {
    const float* x   = (const float*)d_in[0];
    const float* Wih = (const float*)d_in[1];
    const float* Whh = (const float*)d_in[2];
    const float* bih = (const float*)d_in[3];
    const float* bhh = (const float*)d_in[4];
    float* out = (float*)d_out;

    cudaFuncSetAttribute(xg_mma, cudaFuncAttributeMaxDynamicSharedMemorySize, XS_TOTAL);
    cudaFuncSetAttribute(lstm_scan, cudaFuncAttributeMaxDynamicSharedMemorySize,
                         SCAN_SMEM_FLOATS * 4);

    convert_inputs<<<CV_GRID, 256>>>(x, Wih, bih, bhh);
    xg_mma<<<dim3(G4 / MM_BN, (T_STEPS * BATCH) / MM_BM), MM_THR, XS_TOTAL>>>();
    lstm_scan<<<NBLK, SCAN_THR, SCAN_SMEM_FLOATS * 4>>>(Whh, out);
}

// round 7
// speedup vs baseline: 3.0409x; 1.5161x over previous
#include <cuda_runtime.h>
#include <cuda_bf16.h>
#include <cstdint>

#define T_STEPS 512
#define BATCH   64
#define INDIM   1024
#define HID     1024
#define G4      4096

// scan config
#define NBLK     128
#define SCAN_THR 256
// scan smem layout (bytes)
#define WSH_OFF  0
#define WSL_OFF  65536
#define HB_OFF   131072
#define SCAN_SMEM 196608   // 192 KB: W hi/lo (128K) + h 2 bufs x (hi16K+lo16K)

// xg mma config (R5, proven)
#define MM_BM   128
#define MM_BN   128
#define MM_KC   64
#define MM_THR  256

// ---------------------------------------------------------------------------
// Global scratch
// ---------------------------------------------------------------------------
__device__ float g_xg[(size_t)T_STEPS * BATCH * G4];   // [m][j'] permuted, bias included
__device__ __nv_bfloat16 g_hh[2][BATCH * HID];         // h hi, [b][hj], double buffered
__device__ __nv_bfloat16 g_hl[2][BATCH * HID];         // h lo
__device__ __nv_bfloat16 g_xh[(size_t)T_STEPS * BATCH * INDIM];
__device__ __nv_bfloat16 g_xl[(size_t)T_STEPS * BATCH * INDIM];
__device__ __nv_bfloat16 g_wh[(size_t)G4 * INDIM];     // W_ih permuted rows, bf16 hi
__device__ __nv_bfloat16 g_wl[(size_t)G4 * INDIM];     // W_ih bf16 lo
__device__ __nv_bfloat16 g_uh[(size_t)G4 * HID];       // W_hh permuted rows, bf16 hi
__device__ __nv_bfloat16 g_ul[(size_t)G4 * HID];       // W_hh bf16 lo
__device__ float g_bias[G4];
__device__ unsigned int g_count;
__device__ unsigned int g_sense;

// ---------------------------------------------------------------------------
// Ampere-ISA helpers (plain compute_103)
// ---------------------------------------------------------------------------
__device__ __forceinline__ uint32_t smem_to_u32(const void* p) {
    uint32_t a;
    asm("{ .reg .u64 t; cvta.to.shared.u64 t, %1; cvt.u32.u64 %0, t; }" : "=r"(a) : "l"(p));
    return a;
}
__device__ __forceinline__ void ldmx4(uint32_t& r0, uint32_t& r1, uint32_t& r2,
                                      uint32_t& r3, uint32_t a) {
    asm volatile("ldmatrix.sync.aligned.m8n8.x4.shared.b16 {%0,%1,%2,%3}, [%4];"
                 : "=r"(r0), "=r"(r1), "=r"(r2), "=r"(r3) : "r"(a));
}
__device__ __forceinline__ void mma16816(float* d, const uint32_t* a, const uint32_t* b) {
    asm volatile(
        "mma.sync.aligned.m16n8k16.row.col.f32.bf16.bf16.f32 "
        "{%0,%1,%2,%3},{%4,%5,%6,%7},{%8,%9},{%0,%1,%2,%3};"
        : "+f"(d[0]), "+f"(d[1]), "+f"(d[2]), "+f"(d[3])
        : "r"(a[0]), "r"(a[1]), "r"(a[2]), "r"(a[3]), "r"(b[0]), "r"(b[1]));
}
#define CP_ASYNC16(s, g) \
    asm volatile("cp.async.cg.shared.global [%0], [%1], 16;" :: "r"(s), "l"(g) : "memory")
#define CP_COMMIT()  asm volatile("cp.async.commit_group;" ::: "memory")
#define CP_WAIT0()   asm volatile("cp.async.wait_group 0;" ::: "memory")

__device__ __forceinline__ float sigf(float x) {
    return __fdividef(1.0f, 1.0f + __expf(-x));
}
__device__ __forceinline__ float tanh_fast(float x) {
    return __fdividef(2.0f, 1.0f + __expf(-2.0f * x)) - 1.0f;
}

// ---------------------------------------------------------------------------
// Conversion: bf16 hi/lo of x, permuted W_ih AND permuted W_hh; bias; resets
// ---------------------------------------------------------------------------
#define CV_XU 8388608u
#define CV_WU 1048576u
#define CV_UU 1048576u
#define CV_BU 1024u
#define CV_HU 16384u
#define CV_GRID 41028u

__global__ void convert_inputs(const float* __restrict__ x,
                               const float* __restrict__ Wih,
                               const float* __restrict__ Whh,
                               const float* __restrict__ bih,
                               const float* __restrict__ bhh) {
    unsigned u = blockIdx.x * 256u + threadIdx.x;
    if (u < CV_XU) {
        float4 v = __ldg((const float4*)x + u);
        __nv_bfloat162 h01 = __floats2bfloat162_rn(v.x, v.y);
        __nv_bfloat162 h23 = __floats2bfloat162_rn(v.z, v.w);
        __nv_bfloat162 l01 = __floats2bfloat162_rn(v.x - __bfloat162float(h01.x),
                                                   v.y - __bfloat162float(h01.y));
        __nv_bfloat162 l23 = __floats2bfloat162_rn(v.z - __bfloat162float(h23.x),
                                                   v.w - __bfloat162float(h23.y));
        *(__nv_bfloat162*)(g_xh + (size_t)u * 4)     = h01;
        *(__nv_bfloat162*)(g_xh + (size_t)u * 4 + 2) = h23;
        *(__nv_bfloat162*)(g_xl + (size_t)u * 4)     = l01;
        *(__nv_bfloat162*)(g_xl + (size_t)u * 4 + 2) = l23;
    } else if (u < CV_XU + CV_WU) {
        unsigned uw = u - CV_XU;
        int np = uw >> 8;
        int kq = uw & 255;
        int jo = (np & 3) * HID + (np >> 2);
        float4 v = __ldg((const float4*)(Wih + (size_t)jo * INDIM) + kq);
        __nv_bfloat162 h01 = __floats2bfloat162_rn(v.x, v.y);
        __nv_bfloat162 h23 = __floats2bfloat162_rn(v.z, v.w);
        __nv_bfloat162 l01 = __floats2bfloat162_rn(v.x - __bfloat162float(h01.x),
                                                   v.y - __bfloat162float(h01.y));
        __nv_bfloat162 l23 = __floats2bfloat162_rn(v.z - __bfloat162float(h23.x),
                                                   v.w - __bfloat162float(h23.y));
        size_t base = (size_t)np * INDIM + kq * 4;
        *(__nv_bfloat162*)(g_wh + base)     = h01;
        *(__nv_bfloat162*)(g_wh + base + 2) = h23;
        *(__nv_bfloat162*)(g_wl + base)     = l01;
        *(__nv_bfloat162*)(g_wl + base + 2) = l23;
    } else if (u < CV_XU + CV_WU + CV_UU) {
        unsigned uw = u - CV_XU - CV_WU;
        int np = uw >> 8;
        int kq = uw & 255;
        int jo = (np & 3) * HID + (np >> 2);
        float4 v = __ldg((const float4*)(Whh + (size_t)jo * HID) + kq);
        __nv_bfloat162 h01 = __floats2bfloat162_rn(v.x, v.y);
        __nv_bfloat162 h23 = __floats2bfloat162_rn(v.z, v.w);
        __nv_bfloat162 l01 = __floats2bfloat162_rn(v.x - __bfloat162float(h01.x),
                                                   v.y - __bfloat162float(h01.y));
        __nv_bfloat162 l23 = __floats2bfloat162_rn(v.z - __bfloat162float(h23.x),
                                                   v.w - __bfloat162float(h23.y));
        size_t base = (size_t)np * HID + kq * 4;
        *(__nv_bfloat162*)(g_uh + base)     = h01;
        *(__nv_bfloat162*)(g_uh + base + 2) = h23;
        *(__nv_bfloat162*)(g_ul + base)     = l01;
        *(__nv_bfloat162*)(g_ul + base + 2) = l23;
    } else if (u < CV_XU + CV_WU + CV_UU + CV_BU) {
        unsigned ub = u - CV_XU - CV_WU - CV_UU;
        if (ub == 0) { g_count = 0u; g_sense = 0u; }
#pragma unroll
        for (int c = 0; c < 4; c++) {
            int np = ub * 4 + c;
            int jo = (np & 3) * HID + (np >> 2);
            g_bias[np] = bih[jo] + bhh[jo];
        }
    } else if (u < CV_XU + CV_WU + CV_UU + CV_BU + CV_HU) {
        unsigned uh = u - CV_XU - CV_WU - CV_UU - CV_BU;   // 0..16383
        if (uh < 8192u)
            reinterpret_cast<uint4*>(&g_hh[0][0])[uh] = make_uint4(0, 0, 0, 0);
        else
            reinterpret_cast<uint4*>(&g_hl[0][0])[uh - 8192u] = make_uint4(0, 0, 0, 0);
    }
}

// ---------------------------------------------------------------------------
// xg via mma.sync bf16 (3-term split) — R5, proven
// ---------------------------------------------------------------------------
#define XR_AH 0
#define XR_AL 16384
#define XR_BH 32768
#define XR_BL 49152
#define XR_BUF 65536
#define XS_TOTAL (2 * XR_BUF)

__global__ __launch_bounds__(MM_THR, 1) void xg_mma() {
    extern __shared__ char smem[];
    const uint32_t sb = smem_to_u32(smem);
    const int tid = threadIdx.x;
    const int lid = tid & 31;
    const int wid = tid >> 5;
    const int wm  = wid & 3;
    const int wn  = wid >> 2;
    const int n0  = blockIdx.x * MM_BN;
    const int m0  = blockIdx.y * MM_BM;

    const int s_row = tid >> 3;
    const int s_c16 = tid & 7;
    const int a_ml = lid & 15;
    const int a_kh = (lid >> 4) & 1;
    const int b_nl = (lid & 7) + ((lid & 16) ? 8 : 0);
    const int b_kh = (lid >> 3) & 1;

    float acc[2][8][4];
#pragma unroll
    for (int i = 0; i < 2; i++)
#pragma unroll
        for (int j = 0; j < 8; j++)
#pragma unroll
            for (int q = 0; q < 4; q++) acc[i][j][q] = 0.f;

    auto stage = [&](int c, int buf) {
        const int kb = c * MM_KC;
        const uint32_t base = sb + buf * XR_BUF;
#pragma unroll
        for (int p = 0; p < 4; p++) {
            int row = s_row + p * 32;
            uint32_t so = (uint32_t)(row * 128 + ((s_c16 ^ (row & 7)) * 16));
            const __nv_bfloat16* ah = g_xh + (size_t)(m0 + row) * INDIM + kb + s_c16 * 8;
            const __nv_bfloat16* al = g_xl + (size_t)(m0 + row) * INDIM + kb + s_c16 * 8;
            const __nv_bfloat16* bh = g_wh + (size_t)(n0 + row) * INDIM + kb + s_c16 * 8;
            const __nv_bfloat16* bl = g_wl + (size_t)(n0 + row) * INDIM + kb + s_c16 * 8;
            CP_ASYNC16(base + XR_AH + so, ah);
            CP_ASYNC16(base + XR_AL + so, al);
            CP_ASYNC16(base + XR_BH + so, bh);
            CP_ASYNC16(base + XR_BL + so, bl);
        }
        CP_COMMIT();
    };

    stage(0, 0);

#pragma unroll 1
    for (int c = 0; c < 16; c++) {
        CP_WAIT0();
        __syncthreads();
        if (c < 15) stage(c + 1, (c + 1) & 1);

        const uint32_t base = sb + (c & 1) * XR_BUF;
#pragma unroll
        for (int kk = 0; kk < 4; kk++) {
            uint32_t ahf[2][4], alf[2][4];
#pragma unroll
            for (int mf = 0; mf < 2; mf++) {
                int r = wm * 32 + mf * 16 + a_ml;
                uint32_t co = (uint32_t)((((kk * 2 + a_kh) ^ (r & 7)) * 16) + r * 128);
                ldmx4(ahf[mf][0], ahf[mf][1], ahf[mf][2], ahf[mf][3], base + XR_AH + co);
                ldmx4(alf[mf][0], alf[mf][1], alf[mf][2], alf[mf][3], base + XR_AL + co);
            }
#pragma unroll
            for (int np = 0; np < 4; np++) {
                int r = wn * 64 + np * 16 + b_nl;
                uint32_t co = (uint32_t)((((kk * 2 + b_kh) ^ (r & 7)) * 16) + r * 128);
                uint32_t bh[4], bl[4];
                ldmx4(bh[0], bh[1], bh[2], bh[3], base + XR_BH + co);
                ldmx4(bl[0], bl[1], bl[2], bl[3], base + XR_BL + co);
#pragma unroll
                for (int mf = 0; mf < 2; mf++) {
                    mma16816(acc[mf][np * 2 + 0], ahf[mf], &bh[0]);
                    mma16816(acc[mf][np * 2 + 1], ahf[mf], &bh[2]);
                    mma16816(acc[mf][np * 2 + 0], ahf[mf], &bl[0]);
                    mma16816(acc[mf][np * 2 + 1], ahf[mf], &bl[2]);
                    mma16816(acc[mf][np * 2 + 0], alf[mf], &bh[0]);
                    mma16816(acc[mf][np * 2 + 1], alf[mf], &bh[2]);
                }
            }
        }
        __syncthreads();
    }

    const int lr = lid >> 2;
    const int lc = (lid & 3) * 2;
#pragma unroll
    for (int mf = 0; mf < 2; mf++) {
#pragma unroll
        for (int nf = 0; nf < 8; nf++) {
            int m = m0 + wm * 32 + mf * 16 + lr;
            int n = n0 + wn * 64 + nf * 8 + lc;
            float2 bv = __ldg((const float2*)(g_bias + n));
            float2 o0 = make_float2(acc[mf][nf][0] + bv.x, acc[mf][nf][1] + bv.y);
            float2 o1 = make_float2(acc[mf][nf][2] + bv.x, acc[mf][nf][3] + bv.y);
            *reinterpret_cast<float2*>(g_xg + (size_t)m * G4 + n)       = o0;
            *reinterpret_cast<float2*>(g_xg + (size_t)(m + 8) * G4 + n) = o1;
        }
    }
}

// ---------------------------------------------------------------------------
// grid barrier (fence by all threads before arrive)
// ---------------------------------------------------------------------------
__device__ __forceinline__ void grid_bar(unsigned int target) {
    __threadfence();
    __syncthreads();
    if (threadIdx.x == 0) {
        unsigned int a = atomicAdd(&g_count, 1u);
        if (a == NBLK - 1) {
            atomicExch(&g_count, 0u);
            __threadfence();
            atomicExch(&g_sense, target);
        } else {
            volatile unsigned int* s = &g_sense;
            while (*s < target) { __nanosleep(16); }
            __threadfence();
        }
    }
    __syncthreads();
}

// ---------------------------------------------------------------------------
// Tensorized persistent LSTM scan (W_hh slice from g_uh/g_ul).
// ---------------------------------------------------------------------------
__global__ __launch_bounds__(SCAN_THR, 1) void lstm_scan(float* __restrict__ out) {
    extern __shared__ char smem[];
    const uint32_t sb = smem_to_u32(smem);
    const int tid = threadIdx.x;
    const int lid = tid & 31;
    const int wid = tid >> 5;
    const int wm  = wid & 3;          // m-tile: batches wm*16..+15
    const int wn  = wid >> 2;         // n-half: cols wn*16..+15
    const int jt  = blockIdx.x;
    const int j0  = jt * 32;

    const int a_ml = lid & 15;
    const int a_kh = (lid >> 4) & 1;
    const int b_nl = (lid & 7) + ((lid & 16) ? 8 : 0);
    const int b_kh = (lid >> 3) & 1;
    const int lc   = (lid & 3) * 2;
    const int lr   = lid >> 2;

    // --- persistent W_hh slice preload: [32 cols][2048 B] hi/lo, swizzled ---
#pragma unroll 4
    for (int i = 0; i < 16; i++) {
        int g = tid + 256 * i;            // 0..4095
        int row = g >> 7;                 // 0..31
        int slot = g & 127;
        uint4 vh = *(const uint4*)(g_uh + (size_t)(j0 + row) * HID + slot * 8);
        uint4 vl = *(const uint4*)(g_ul + (size_t)(j0 + row) * HID + slot * 8);
        uint32_t doff = (uint32_t)(row * 2048 + (slot >> 3) * 128 +
                                   (((slot & 7) ^ (row & 7)) * 16));
        *(uint4*)(smem + WSH_OFF + doff) = vh;
        *(uint4*)(smem + WSL_OFF + doff) = vl;
    }
    __syncthreads();

    const int st_r = tid >> 2;          // row 0..63
    const int st_s = (tid & 3) * 4;     // 4 slots of 16

    const int a_row = wm * 16 + a_ml;
    const uint32_t a_roff = (uint32_t)(a_row * 256);
    const int pa = a_ml & 7;
    const int b_row = wn * 16 + b_nl;
    const uint32_t bh_base = sb + WSH_OFF + (uint32_t)(b_row * 2048);
    const uint32_t bl_base = sb + WSL_OFF + (uint32_t)(b_row * 2048);
    const int pb = b_nl & 7;

    float c_[4] = {0.f, 0.f, 0.f, 0.f};

#pragma unroll 1
    for (int t = 0; t < T_STEPS; t++) {
        const int cur = t & 1, nxt = cur ^ 1;
        const __nv_bfloat16* hhs = g_hh[cur];
        const __nv_bfloat16* hls = g_hl[cur];

        // xg prefetch (independent; hidden by k-loop)
        float2 xv[2][2];
        {
            const float* xgt = g_xg + (size_t)t * (BATCH * G4);
#pragma unroll
            for (int nt = 0; nt < 2; nt++)
#pragma unroll
                for (int rr = 0; rr < 2; rr++) {
                    int b = wm * 16 + lr + rr * 8;
                    int col = j0 + wn * 16 + nt * 8 + lc;
                    xv[nt][rr] = *(const float2*)(xgt + (size_t)b * G4 + col);
                }
        }

        float acc[2][4];
#pragma unroll
        for (int nt = 0; nt < 2; nt++)
#pragma unroll
            for (int q = 0; q < 4; q++) acc[nt][q] = 0.f;

        // stage chunk 0
        {
            const __nv_bfloat16* sH = hhs + st_r * HID;
            const __nv_bfloat16* sL = hls + st_r * HID;
            uint32_t dH = sb + HB_OFF + (uint32_t)(st_r * 256);
#pragma unroll
            for (int j = 0; j < 4; j++) {
                int slot = st_s + j;
                uint32_t doff = (uint32_t)((slot >> 3) * 128 + (((slot & 7) ^ (st_r & 7)) * 16));
                CP_ASYNC16(dH + doff, sH + slot * 8);
                CP_ASYNC16(dH + 16384 + doff, sL + slot * 8);
            }
            CP_COMMIT();
        }

        int buf = 0;
#pragma unroll 1
        for (int c = 0; c < 8; c++) {
            CP_WAIT0();
            __syncthreads();
            if (c < 7) {
                const __nv_bfloat16* sH = hhs + st_r * HID + (c + 1) * 128;
                const __nv_bfloat16* sL = hls + st_r * HID + (c + 1) * 128;
                uint32_t dH = sb + HB_OFF + (uint32_t)((buf ^ 1) * 32768 + st_r * 256);
#pragma unroll
                for (int j = 0; j < 4; j++) {
                    int slot = st_s + j;
                    uint32_t doff = (uint32_t)((slot >> 3) * 128 +
                                               (((slot & 7) ^ (st_r & 7)) * 16));
                    CP_ASYNC16(dH + doff, sH + slot * 8);
                    CP_ASYNC16(dH + 16384 + doff, sL + slot * 8);
                }
                CP_COMMIT();
            }

            const uint32_t hbH = sb + HB_OFF + (uint32_t)(buf * 32768);
            const uint32_t hbL = hbH + 16384;
#pragma unroll
            for (int kk = 0; kk < 8; kk++) {
                uint32_t aoff = a_roff + (uint32_t)((kk >> 2) * 128 +
                                ((((kk & 3) * 2 + a_kh) ^ pa) * 16));
                uint32_t ahf[4], alf[4];
                ldmx4(ahf[0], ahf[1], ahf[2], ahf[3], hbH + aoff);
                ldmx4(alf[0], alf[1], alf[2], alf[3], hbL + aoff);
                int gk = c * 8 + kk;
                uint32_t boff = (uint32_t)((gk >> 2) * 128 +
                                ((((gk & 3) * 2 + b_kh) ^ pb) * 16));
                uint32_t bh[4], bl[4];
                ldmx4(bh[0], bh[1], bh[2], bh[3], bh_base + boff);
                ldmx4(bl[0], bl[1], bl[2], bl[3], bl_base + boff);
                mma16816(acc[0], ahf, &bh[0]);
                mma16816(acc[1], ahf, &bh[2]);
                mma16816(acc[0], ahf, &bl[0]);
                mma16816(acc[1], ahf, &bl[2]);
                mma16816(acc[0], alf, &bh[0]);
                mma16816(acc[1], alf, &bh[2]);
            }
            buf ^= 1;
        }

        // ---- epilogue: +xg, gate pair exchange, state update, h write ----
        float hn[4];
#pragma unroll
        for (int nt = 0; nt < 2; nt++) {
#pragma unroll
            for (int rr = 0; rr < 2; rr++) {
                float g0 = acc[nt][rr * 2 + 0] + xv[nt][rr].x;
                float g1 = acc[nt][rr * 2 + 1] + xv[nt][rr].y;
                float p0 = __shfl_xor_sync(0xffffffffu, g0, 1);
                float p1 = __shfl_xor_sync(0xffffffffu, g1, 1);
                int ci = nt * 2 + rr;
                float gi = sigf(g0);
                float gf = sigf(g1);
                float gg = tanh_fast(p0);
                float go = sigf(p1);
                float cc = gf * c_[ci] + gi * gg;
                c_[ci] = cc;
                hn[ci] = go * tanh_fast(cc);
            }
        }
        if ((lid & 1) == 0) {
#pragma unroll
            for (int nt = 0; nt < 2; nt++) {
                int hjg = jt * 8 + ((wn * 16 + nt * 8 + lc) >> 2);
#pragma unroll
                for (int rr = 0; rr < 2; rr++) {
                    int b = wm * 16 + lr + rr * 8;
                    float v = hn[nt * 2 + rr];
                    __nv_bfloat16 hi = __float2bfloat16(v);
                    __nv_bfloat16 lo = __float2bfloat16(v - __bfloat162float(hi));
                    g_hh[nxt][b * HID + hjg] = hi;
                    g_hl[nxt][b * HID + hjg] = lo;
                    if (t == T_STEPS - 1) out[b * HID + hjg] = v;
                }
            }
        }

        if (t != T_STEPS - 1) grid_bar((unsigned int)(t + 1));
    }
}

// ---------------------------------------------------------------------------
extern "C" void kernel_launch(void* const* d_in, const int* in_sizes, int n_in,
                              void* d_out, int out_size) {
    const float* x   = (const float*)d_in[0];
    const float* Wih = (const float*)d_in[1];
    const float* Whh = (const float*)d_in[2];
    const float* bih = (const float*)d_in[3];
    const float* bhh = (const float*)d_in[4];
    float* out = (float*)d_out;

    cudaFuncSetAttribute(xg_mma, cudaFuncAttributeMaxDynamicSharedMemorySize, XS_TOTAL);
    cudaFuncSetAttribute(lstm_scan, cudaFuncAttributeMaxDynamicSharedMemorySize, SCAN_SMEM);

    convert_inputs<<<CV_GRID, 256>>>(x, Wih, Whh, bih, bhh);
    xg_mma<<<dim3(G4 / MM_BN, (T_STEPS * BATCH) / MM_BM), MM_THR, XS_TOTAL>>>();
    lstm_scan<<<NBLK, SCAN_THR, SCAN_SMEM>>>(out);
}